// round 2
// baseline (speedup 1.0000x reference)
#include <cuda_runtime.h>
#include <cuda_bf16.h>
#include <math.h>

#define NN 50000
#define EE 1600000
#define FF 256
#define KHOP 3
#define GK 768
#define GN 256

// ---------------- scratch (device globals; no allocations allowed) ----------------
__device__ float g_u[KHOP * FF];
__device__ float g_v[KHOP * FF];
__device__ float g_s_src[KHOP * NN];
__device__ float g_s_dst[KHOP * NN];
__device__ float g_rowsum[KHOP * NN];
__device__ int   g_deg[KHOP * NN];
__device__ int   g_ptr[KHOP * NN];
__device__ int   g_fill[KHOP * NN];
__device__ int   g_csr_dst[(size_t)KHOP * EE];
__device__ float g_csr_w[(size_t)KHOP * EE];
__device__ float g_agg[(size_t)NN * GK];   // [N, 768] hop-blocked columns

// ---------------- kernels ----------------

__global__ void zero_kernel() {
    int i = blockIdx.x * blockDim.x + threadIdx.x;
    if (i < KHOP * NN) { g_deg[i] = 0; g_rowsum[i] = 0.f; }
}

// u_z = W_z @ a_src(z), v_z = W_z @ a_dst(z)
__global__ void uv_kernel(const float* __restrict__ W, const float* __restrict__ a) {
    int z = blockIdx.x;
    int k = threadIdx.x;            // 0..255
    const float* wrow = W + (size_t)(z * FF + k) * GN;
    const float* au = a + z * 2 * FF;
    const float* av = au + FF;
    float u = 0.f, v = 0.f;
    #pragma unroll 8
    for (int j = 0; j < FF; j++) {
        float w = wrow[j];
        u = fmaf(w, au[j], u);
        v = fmaf(w, av[j], v);
    }
    g_u[z * FF + k] = u;
    g_v[z * FF + k] = v;
}

// s_src[z][n] = X[n]·u_z ; s_dst[z][n] = X[n]·v_z  (warp per node)
__global__ void __launch_bounds__(256) scores_kernel(const float* __restrict__ X) {
    __shared__ float su[KHOP][FF];
    __shared__ float sv[KHOP][FF];
    int tid = threadIdx.x;
    for (int i = tid; i < KHOP * FF; i += 256) {
        su[i / FF][i % FF] = g_u[i];
        sv[i / FF][i % FF] = g_v[i];
    }
    __syncthreads();
    int warp = tid >> 5, lane = tid & 31;
    int n = blockIdx.x * 8 + warp;
    if (n >= NN) return;
    float xr[8];
    #pragma unroll
    for (int j = 0; j < 8; j++) xr[j] = X[(size_t)n * FF + j * 32 + lane];
    #pragma unroll
    for (int z = 0; z < KHOP; z++) {
        float du = 0.f, dv = 0.f;
        #pragma unroll
        for (int j = 0; j < 8; j++) {
            du = fmaf(xr[j], su[z][j * 32 + lane], du);
            dv = fmaf(xr[j], sv[z][j * 32 + lane], dv);
        }
        #pragma unroll
        for (int off = 16; off > 0; off >>= 1) {
            du += __shfl_xor_sync(0xFFFFFFFFu, du, off);
            dv += __shfl_xor_sync(0xFFFFFFFFu, dv, off);
        }
        if (lane == 0) {
            g_s_src[z * NN + n] = du;
            g_s_dst[z * NN + n] = dv;
        }
    }
}

__global__ void hist_kernel(const int* __restrict__ kel) {
    int z = blockIdx.y;
    int e = blockIdx.x * 256 + threadIdx.x;
    if (e >= EE) return;
    int src = kel[(size_t)z * 2 * EE + e];
    atomicAdd(&g_deg[z * NN + src], 1);
}

// per-hop exclusive scan of degrees (single block of 1024, chunked)
__global__ void __launch_bounds__(1024) scan_kernel() {
    int z = blockIdx.x;
    __shared__ int s[1024];
    int tid = threadIdx.x;
    int carry = 0;
    for (int base = 0; base < NN; base += 1024) {
        int i = base + tid;
        int v = (i < NN) ? g_deg[z * NN + i] : 0;
        s[tid] = v;
        __syncthreads();
        #pragma unroll
        for (int off = 1; off < 1024; off <<= 1) {
            int t = (tid >= off) ? s[tid - off] : 0;
            __syncthreads();
            s[tid] += t;
            __syncthreads();
        }
        int excl = s[tid] - v;
        if (i < NN) {
            g_ptr[z * NN + i] = carry + excl;
            g_fill[z * NN + i] = carry + excl;
        }
        int tot = s[1023];
        __syncthreads();
        carry += tot;
    }
}

// CSR fill + edge weight + rowsum
__global__ void build_kernel(const int* __restrict__ kel) {
    int z = blockIdx.y;
    int e = blockIdx.x * 256 + threadIdx.x;
    if (e >= EE) return;
    int src = kel[(size_t)z * 2 * EE + e];
    int dst = kel[(size_t)z * 2 * EE + EE + e];
    float sc = g_s_src[z * NN + src] + g_s_dst[z * NN + dst];
    float l = sc > 0.f ? sc : 0.2f * sc;       // leaky_relu(alpha=0.2)
    float w = expf(-l);
    int idx = atomicAdd(&g_fill[z * NN + src], 1);
    g_csr_dst[(size_t)z * EE + idx] = dst;
    g_csr_w[(size_t)z * EE + idx] = w;
    atomicAdd(&g_rowsum[z * NN + src], w);
}

// agg[n][z*256 + t] = coef_z * (sum_e w_e X[dst_e][t]) / rowsum
__global__ void __launch_bounds__(256) aggregate_kernel(const float* __restrict__ X) {
    const int z = blockIdx.y;
    const int n = blockIdx.x;
    const int tid = threadIdx.x;
    __shared__ int   sd[128];
    __shared__ float sw[128];
    const int start = g_ptr[z * NN + n];
    const int d     = g_deg[z * NN + n];
    const int* __restrict__ cd = g_csr_dst + (size_t)z * EE + start;
    const float* __restrict__ cw = g_csr_w + (size_t)z * EE + start;
    float acc = 0.f;
    for (int base = 0; base < d; base += 128) {
        int cnt = min(128, d - base);
        __syncthreads();
        if (tid < cnt) { sd[tid] = cd[base + tid]; sw[tid] = cw[base + tid]; }
        __syncthreads();
        int j = 0;
        for (; j + 4 <= cnt; j += 4) {
            float x0 = X[(size_t)sd[j + 0] * FF + tid];
            float x1 = X[(size_t)sd[j + 1] * FF + tid];
            float x2 = X[(size_t)sd[j + 2] * FF + tid];
            float x3 = X[(size_t)sd[j + 3] * FF + tid];
            acc = fmaf(sw[j + 0], x0, acc);
            acc = fmaf(sw[j + 1], x1, acc);
            acc = fmaf(sw[j + 2], x2, acc);
            acc = fmaf(sw[j + 3], x3, acc);
        }
        for (; j < cnt; j++)
            acc = fmaf(sw[j], X[(size_t)sd[j] * FF + tid], acc);
    }
    const float coef = (z == 0) ? 0.5f : (z == 1) ? 0.25f : 0.125f;
    float rs = g_rowsum[z * NN + n];
    g_agg[(size_t)n * GK + z * FF + tid] = coef * acc / rs;
}

__device__ __forceinline__ float elu1(float x) {
    return x > 0.f ? x : expm1f(x);
}

// C[50000,256] = elu( g_agg[50000,768] @ W[768,256] )
__global__ void __launch_bounds__(256) gemm_elu_kernel(const float* __restrict__ B,
                                                       float* __restrict__ C) {
    const int M = NN;
    __shared__ float As[2][16][128];
    __shared__ float Bs[2][16][128];
    const int rowBase = blockIdx.x * 128;
    const int colBase = blockIdx.y * 128;
    const int tid = threadIdx.x;
    const int aRow = tid >> 2;            // 0..63
    const int aCol = (tid & 3) << 2;      // 0,4,8,12
    const int bRow = tid >> 5;            // 0..7
    const int bCol = (tid & 31) << 2;     // 0..124
    const int tr = (tid >> 4) << 3;       // 0..120
    const int tc = (tid & 15) << 3;       // 0..120

    float acc[8][8];
    #pragma unroll
    for (int i = 0; i < 8; i++)
        #pragma unroll
        for (int j = 0; j < 8; j++) acc[i][j] = 0.f;

    float4 aReg[2], bReg[2];

    // prologue: tile k0 = 0
    #pragma unroll
    for (int i = 0; i < 2; i++) {
        int r = rowBase + aRow + i * 64;
        aReg[i] = (r < M) ? *(const float4*)(g_agg + (size_t)r * GK + aCol)
                          : make_float4(0.f, 0.f, 0.f, 0.f);
        bReg[i] = *(const float4*)(B + (size_t)(bRow + i * 8) * GN + colBase + bCol);
    }
    #pragma unroll
    for (int i = 0; i < 2; i++) {
        As[0][aCol + 0][aRow + i * 64] = aReg[i].x;
        As[0][aCol + 1][aRow + i * 64] = aReg[i].y;
        As[0][aCol + 2][aRow + i * 64] = aReg[i].z;
        As[0][aCol + 3][aRow + i * 64] = aReg[i].w;
        *(float4*)&Bs[0][bRow + i * 8][bCol] = bReg[i];
    }
    __syncthreads();

    int buf = 0;
    const int nT = GK / 16;   // 48
    for (int t = 0; t < nT; t++) {
        if (t + 1 < nT) {
            int k0 = (t + 1) * 16;
            #pragma unroll
            for (int i = 0; i < 2; i++) {
                int r = rowBase + aRow + i * 64;
                aReg[i] = (r < M) ? *(const float4*)(g_agg + (size_t)r * GK + k0 + aCol)
                                  : make_float4(0.f, 0.f, 0.f, 0.f);
                bReg[i] = *(const float4*)(B + (size_t)(k0 + bRow + i * 8) * GN + colBase + bCol);
            }
        }
        #pragma unroll
        for (int kk = 0; kk < 16; kk++) {
            float af[8], bf[8];
            #pragma unroll
            for (int i = 0; i < 8; i++) af[i] = As[buf][kk][tr + i];
            #pragma unroll
            for (int j = 0; j < 8; j++) bf[j] = Bs[buf][kk][tc + j];
            #pragma unroll
            for (int i = 0; i < 8; i++)
                #pragma unroll
                for (int j = 0; j < 8; j++)
                    acc[i][j] = fmaf(af[i], bf[j], acc[i][j]);
        }
        if (t + 1 < nT) {
            int nb = buf ^ 1;
            #pragma unroll
            for (int i = 0; i < 2; i++) {
                As[nb][aCol + 0][aRow + i * 64] = aReg[i].x;
                As[nb][aCol + 1][aRow + i * 64] = aReg[i].y;
                As[nb][aCol + 2][aRow + i * 64] = aReg[i].z;
                As[nb][aCol + 3][aRow + i * 64] = aReg[i].w;
                *(float4*)&Bs[nb][bRow + i * 8][bCol] = bReg[i];
            }
            __syncthreads();
            buf = nb;
        }
    }

    #pragma unroll
    for (int i = 0; i < 8; i++) {
        int r = rowBase + tr + i;
        if (r < M) {
            #pragma unroll
            for (int j = 0; j < 8; j += 4) {
                float4 v;
                v.x = elu1(acc[i][j + 0]);
                v.y = elu1(acc[i][j + 1]);
                v.z = elu1(acc[i][j + 2]);
                v.w = elu1(acc[i][j + 3]);
                *(float4*)(C + (size_t)r * GN + colBase + tc + j) = v;
            }
        }
    }
}

// ---------------- launch ----------------
extern "C" void kernel_launch(void* const* d_in, const int* in_sizes, int n_in,
                              void* d_out, int out_size) {
    const float* X   = (const float*)d_in[0];   // [50000, 256]
    const int*   kel = (const int*)d_in[1];     // [3, 2, 1600000]
    const float* W   = (const float*)d_in[2];   // [768, 256]
    const float* a   = (const float*)d_in[3];   // [1, 1536]
    float* out = (float*)d_out;

    zero_kernel<<<(KHOP * NN + 255) / 256, 256>>>();
    uv_kernel<<<KHOP, 256>>>(W, a);
    scores_kernel<<<NN / 8, 256>>>(X);
    hist_kernel<<<dim3(EE / 256, KHOP), 256>>>(kel);
    scan_kernel<<<KHOP, 1024>>>();
    build_kernel<<<dim3(EE / 256, KHOP), 256>>>(kel);
    aggregate_kernel<<<dim3(NN, KHOP), 256>>>(X);
    gemm_elu_kernel<<<dim3((NN + 127) / 128, GN / 128), 256>>>(W, out);
}

// round 3
// speedup vs baseline: 1.1420x; 1.1420x over previous
#include <cuda_runtime.h>
#include <cuda_bf16.h>
#include <math.h>

#define NN 50000
#define EE 1600000
#define FF 256
#define KHOP 3
#define GN 256

typedef unsigned long long ull;

// ---------------- scratch (device globals; no allocations allowed) ----------------
__device__ float g_u[KHOP * FF];
__device__ float g_v[KHOP * FF];
__device__ float g_s_src[KHOP * NN];
__device__ float g_s_dst[KHOP * NN];
__device__ float g_rowsum[KHOP * NN];
__device__ int   g_deg[KHOP * NN];
__device__ int   g_ptr[KHOP * NN];
__device__ int   g_fill[KHOP * NN];
__device__ int2  g_csr[(size_t)KHOP * EE];     // (dst, w-as-int) packed
__device__ float g_Y[(size_t)NN * FF];         // per-hop Y = X @ W_z (reused)
__device__ float g_hacc[(size_t)NN * FF];      // hop accumulator

// ---------------- f32x2 packed-FMA helpers (Blackwell double-rate fp32) ----------
__device__ __forceinline__ ull pk2(float x, float y) {
    ull r; asm("mov.b64 %0, {%1, %2};" : "=l"(r) : "f"(x), "f"(y)); return r;
}
__device__ __forceinline__ void fma2(ull& d, ull a, ull b) {
    asm("fma.rn.f32x2 %0, %1, %2, %0;" : "+l"(d) : "l"(a), "l"(b));
}
__device__ __forceinline__ float2 upk2(ull v) {
    float2 r; asm("mov.b64 {%0, %1}, %2;" : "=f"(r.x), "=f"(r.y) : "l"(v)); return r;
}
__device__ __forceinline__ float elu1(float x) { return x > 0.f ? x : expm1f(x); }

// ---------------- kernels ----------------

__global__ void zero_kernel() {
    int i = blockIdx.x * blockDim.x + threadIdx.x;
    if (i < KHOP * NN) { g_deg[i] = 0; g_rowsum[i] = 0.f; }
}

// u_z = W_z @ a_src(z), v_z = W_z @ a_dst(z)
__global__ void uv_kernel(const float* __restrict__ W, const float* __restrict__ a) {
    int z = blockIdx.x;
    int k = threadIdx.x;
    const float* wrow = W + (size_t)(z * FF + k) * GN;
    const float* au = a + z * 2 * FF;
    const float* av = au + FF;
    float u = 0.f, v = 0.f;
    #pragma unroll 8
    for (int j = 0; j < FF; j++) {
        float w = wrow[j];
        u = fmaf(w, au[j], u);
        v = fmaf(w, av[j], v);
    }
    g_u[z * FF + k] = u;
    g_v[z * FF + k] = v;
}

// s_src[z][n] = X[n]·u_z ; s_dst[z][n] = X[n]·v_z  (warp per node)
__global__ void __launch_bounds__(256) scores_kernel(const float* __restrict__ X) {
    __shared__ float su[KHOP][FF];
    __shared__ float sv[KHOP][FF];
    int tid = threadIdx.x;
    for (int i = tid; i < KHOP * FF; i += 256) {
        su[i / FF][i % FF] = g_u[i];
        sv[i / FF][i % FF] = g_v[i];
    }
    __syncthreads();
    int warp = tid >> 5, lane = tid & 31;
    int n = blockIdx.x * 8 + warp;
    if (n >= NN) return;
    float xr[8];
    #pragma unroll
    for (int j = 0; j < 8; j++) xr[j] = X[(size_t)n * FF + j * 32 + lane];
    #pragma unroll
    for (int z = 0; z < KHOP; z++) {
        float du = 0.f, dv = 0.f;
        #pragma unroll
        for (int j = 0; j < 8; j++) {
            du = fmaf(xr[j], su[z][j * 32 + lane], du);
            dv = fmaf(xr[j], sv[z][j * 32 + lane], dv);
        }
        #pragma unroll
        for (int off = 16; off > 0; off >>= 1) {
            du += __shfl_xor_sync(0xFFFFFFFFu, du, off);
            dv += __shfl_xor_sync(0xFFFFFFFFu, dv, off);
        }
        if (lane == 0) {
            g_s_src[z * NN + n] = du;
            g_s_dst[z * NN + n] = dv;
        }
    }
}

__global__ void hist_kernel(const int* __restrict__ kel) {
    int z = blockIdx.y;
    int e = blockIdx.x * 256 + threadIdx.x;
    if (e >= EE) return;
    int src = kel[(size_t)z * 2 * EE + e];
    atomicAdd(&g_deg[z * NN + src], 1);
}

// per-hop exclusive scan of degrees: warp-shuffle based, 2 barriers per chunk
__global__ void __launch_bounds__(1024) scan_kernel() {
    int z = blockIdx.x;
    __shared__ int wsum[32];
    int tid = threadIdx.x, lane = tid & 31, wid = tid >> 5;
    int carry = 0;
    for (int base = 0; base < NN; base += 1024) {
        int i = base + tid;
        int v = (i < NN) ? g_deg[z * NN + i] : 0;
        int x = v;
        #pragma unroll
        for (int off = 1; off < 32; off <<= 1) {
            int t = __shfl_up_sync(0xFFFFFFFFu, x, off);
            if (lane >= off) x += t;
        }
        if (lane == 31) wsum[wid] = x;
        __syncthreads();
        if (wid == 0) {
            int s = wsum[lane];
            #pragma unroll
            for (int off = 1; off < 32; off <<= 1) {
                int t = __shfl_up_sync(0xFFFFFFFFu, s, off);
                if (lane >= off) s += t;
            }
            wsum[lane] = s;
        }
        __syncthreads();
        int woff = wid ? wsum[wid - 1] : 0;
        int excl = carry + woff + x - v;
        if (i < NN) { g_ptr[z * NN + i] = excl; g_fill[z * NN + i] = excl; }
        int tot = wsum[31];
        __syncthreads();
        carry += tot;
    }
}

// CSR fill (packed int2) + edge weight + rowsum
__global__ void build_kernel(const int* __restrict__ kel) {
    int z = blockIdx.y;
    int e = blockIdx.x * 256 + threadIdx.x;
    if (e >= EE) return;
    int src = kel[(size_t)z * 2 * EE + e];
    int dst = kel[(size_t)z * 2 * EE + EE + e];
    float sc = g_s_src[z * NN + src] + g_s_dst[z * NN + dst];
    float l = sc > 0.f ? sc : 0.2f * sc;           // leaky_relu(alpha=0.2)
    float w = expf(-l);
    int idx = atomicAdd(&g_fill[z * NN + src], 1);
    g_csr[(size_t)z * EE + idx] = make_int2(dst, __float_as_int(w));
    atomicAdd(&g_rowsum[z * NN + src], w);
}

// Y[M,256] = X[M,256] @ B[256,256], fp32 via packed f32x2 FMA, 128x128 tiles
__global__ void __launch_bounds__(256, 2) gemm_kernel(const float* __restrict__ A,
                                                      const float* __restrict__ B,
                                                      float* __restrict__ C) {
    const int M = NN;
    __shared__ float As[2][16][128];
    __shared__ float Bs[2][16][128];
    const int rowBase = blockIdx.x * 128;
    const int colBase = blockIdx.y * 128;
    const int tid = threadIdx.x;
    const int aRow = tid >> 2;            // 0..63
    const int aCol = (tid & 3) << 2;      // 0,4,8,12
    const int bRow = tid >> 5;            // 0..7
    const int bCol = (tid & 31) << 2;     // 0..124
    const int tr = (tid >> 4) << 3;       // 0..120
    const int tc = (tid & 15) << 3;       // 0..120

    ull acc2[8][4];
    #pragma unroll
    for (int i = 0; i < 8; i++)
        #pragma unroll
        for (int j = 0; j < 4; j++) acc2[i][j] = 0ull;

    float4 aReg[2], bReg[2];

    // prologue: k-tile 0
    #pragma unroll
    for (int i = 0; i < 2; i++) {
        int r = rowBase + aRow + i * 64;
        aReg[i] = (r < M) ? *(const float4*)(A + (size_t)r * FF + aCol)
                          : make_float4(0.f, 0.f, 0.f, 0.f);
        bReg[i] = *(const float4*)(B + (size_t)(bRow + i * 8) * GN + colBase + bCol);
    }
    #pragma unroll
    for (int i = 0; i < 2; i++) {
        As[0][aCol + 0][aRow + i * 64] = aReg[i].x;
        As[0][aCol + 1][aRow + i * 64] = aReg[i].y;
        As[0][aCol + 2][aRow + i * 64] = aReg[i].z;
        As[0][aCol + 3][aRow + i * 64] = aReg[i].w;
        *(float4*)&Bs[0][bRow + i * 8][bCol] = bReg[i];
    }
    __syncthreads();

    int buf = 0;
    const int nT = FF / 16;   // 16
    for (int t = 0; t < nT; t++) {
        if (t + 1 < nT) {
            int k0 = (t + 1) * 16;
            #pragma unroll
            for (int i = 0; i < 2; i++) {
                int r = rowBase + aRow + i * 64;
                aReg[i] = (r < M) ? *(const float4*)(A + (size_t)r * FF + k0 + aCol)
                                  : make_float4(0.f, 0.f, 0.f, 0.f);
                bReg[i] = *(const float4*)(B + (size_t)(k0 + bRow + i * 8) * GN + colBase + bCol);
            }
        }
        #pragma unroll
        for (int kk = 0; kk < 16; kk++) {
            float4 a0 = *(const float4*)&As[buf][kk][tr];
            float4 a1 = *(const float4*)&As[buf][kk][tr + 4];
            const ull* bp = (const ull*)&Bs[buf][kk][tc];
            ull b0 = bp[0], b1 = bp[1], b2 = bp[2], b3 = bp[3];
            ull ad[8];
            ad[0] = pk2(a0.x, a0.x); ad[1] = pk2(a0.y, a0.y);
            ad[2] = pk2(a0.z, a0.z); ad[3] = pk2(a0.w, a0.w);
            ad[4] = pk2(a1.x, a1.x); ad[5] = pk2(a1.y, a1.y);
            ad[6] = pk2(a1.z, a1.z); ad[7] = pk2(a1.w, a1.w);
            #pragma unroll
            for (int i = 0; i < 8; i++) {
                fma2(acc2[i][0], ad[i], b0);
                fma2(acc2[i][1], ad[i], b1);
                fma2(acc2[i][2], ad[i], b2);
                fma2(acc2[i][3], ad[i], b3);
            }
        }
        if (t + 1 < nT) {
            int nb = buf ^ 1;
            #pragma unroll
            for (int i = 0; i < 2; i++) {
                As[nb][aCol + 0][aRow + i * 64] = aReg[i].x;
                As[nb][aCol + 1][aRow + i * 64] = aReg[i].y;
                As[nb][aCol + 2][aRow + i * 64] = aReg[i].z;
                As[nb][aCol + 3][aRow + i * 64] = aReg[i].w;
                *(float4*)&Bs[nb][bRow + i * 8][bCol] = bReg[i];
            }
            __syncthreads();
            buf = nb;
        }
    }

    #pragma unroll
    for (int i = 0; i < 8; i++) {
        int r = rowBase + tr + i;
        if (r < M) {
            float2 p0 = upk2(acc2[i][0]), p1 = upk2(acc2[i][1]);
            float2 p2 = upk2(acc2[i][2]), p3 = upk2(acc2[i][3]);
            *(float4*)(C + (size_t)r * GN + colBase + tc)     = make_float4(p0.x, p0.y, p1.x, p1.y);
            *(float4*)(C + (size_t)r * GN + colBase + tc + 4) = make_float4(p2.x, p2.y, p3.x, p3.y);
        }
    }
}

// out-space aggregation for hop z:
//   val = coef * (sum_e w_e Y[dst_e][t]) / rowsum[n]
//   mode 0: hacc = val ; mode 1: hacc += val ; mode 2: d_out = elu(hacc + val)
__global__ void __launch_bounds__(256) aggregate_kernel(const float* __restrict__ Y,
                                                        int z, float coef, int mode,
                                                        float* __restrict__ dst_buf) {
    const int n = blockIdx.x;
    const int tid = threadIdx.x;
    __shared__ int2 se[128];
    const int start = g_ptr[z * NN + n];
    const int d     = g_deg[z * NN + n];
    const int2* __restrict__ ce = g_csr + (size_t)z * EE + start;
    float acc = 0.f;
    for (int base = 0; base < d; base += 128) {
        int cnt = min(128, d - base);
        __syncthreads();
        if (tid < cnt) se[tid] = ce[base + tid];
        __syncthreads();
        int j = 0;
        for (; j + 4 <= cnt; j += 4) {
            int2 e0 = se[j + 0], e1 = se[j + 1], e2 = se[j + 2], e3 = se[j + 3];
            float x0 = Y[(size_t)e0.x * FF + tid];
            float x1 = Y[(size_t)e1.x * FF + tid];
            float x2 = Y[(size_t)e2.x * FF + tid];
            float x3 = Y[(size_t)e3.x * FF + tid];
            acc = fmaf(__int_as_float(e0.y), x0, acc);
            acc = fmaf(__int_as_float(e1.y), x1, acc);
            acc = fmaf(__int_as_float(e2.y), x2, acc);
            acc = fmaf(__int_as_float(e3.y), x3, acc);
        }
        for (; j < cnt; j++)
            acc = fmaf(__int_as_float(se[j].y), Y[(size_t)se[j].x * FF + tid], acc);
    }
    float val = coef * acc / g_rowsum[z * NN + n];
    size_t o = (size_t)n * FF + tid;
    if (mode == 0)      g_hacc[o] = val;
    else if (mode == 1) g_hacc[o] += val;
    else                dst_buf[o] = elu1(g_hacc[o] + val);
}

// ---------------- launch ----------------
extern "C" void kernel_launch(void* const* d_in, const int* in_sizes, int n_in,
                              void* d_out, int out_size) {
    const float* X   = (const float*)d_in[0];   // [50000, 256]
    const int*   kel = (const int*)d_in[1];     // [3, 2, 1600000]
    const float* W   = (const float*)d_in[2];   // [768, 256]
    const float* a   = (const float*)d_in[3];   // [1, 1536]
    float* out = (float*)d_out;

    zero_kernel<<<(KHOP * NN + 255) / 256, 256>>>();
    uv_kernel<<<KHOP, 256>>>(W, a);
    scores_kernel<<<NN / 8, 256>>>(X);
    hist_kernel<<<dim3(EE / 256, KHOP), 256>>>(kel);
    scan_kernel<<<KHOP, 1024>>>();
    build_kernel<<<dim3(EE / 256, KHOP), 256>>>(kel);

    float* Y;
    cudaGetSymbolAddress((void**)&Y, g_Y);
    const float coef[KHOP] = {0.5f, 0.25f, 0.125f};
    for (int z = 0; z < KHOP; z++) {
        gemm_kernel<<<dim3((NN + 127) / 128, GN / 128), 256>>>(X, W + (size_t)z * FF * GN, Y);
        aggregate_kernel<<<NN, 256>>>(Y, z, coef[z], (z == KHOP - 1) ? 2 : (z == 0 ? 0 : 1), out);
    }
}

// round 5
// speedup vs baseline: 1.3781x; 1.2067x over previous
#include <cuda_runtime.h>
#include <cuda_bf16.h>
#include <math.h>
#include <stdint.h>

#define NN 50000
#define EE 1600000
#define FF 256
#define KHOP 3
#define GN 256

// ---------------- scratch (device globals; no allocations allowed) ----------------
__device__ float g_u[KHOP * FF];
__device__ float g_v[KHOP * FF];
__device__ float g_s_src[KHOP * NN];
__device__ float g_s_dst[KHOP * NN];
__device__ float g_rowsum[KHOP * NN];
__device__ int   g_deg[KHOP * NN];
__device__ int   g_ptr[KHOP * NN];
__device__ int   g_fill[KHOP * NN];
__device__ int2  g_csr[(size_t)KHOP * EE];          // (dst, w-as-int)
__device__ float g_Y[(size_t)NN * FF];               // per-hop Y = X @ W_z (reused)
__device__ float g_hacc[(size_t)NN * FF];            // hop accumulator
__device__ __nv_bfloat16 g_Xhi[(size_t)NN * FF];
__device__ __nv_bfloat16 g_Xlo[(size_t)NN * FF];
__device__ __nv_bfloat16 g_Wthi[KHOP * FF * GN];     // transposed: [z][n][k]
__device__ __nv_bfloat16 g_Wtlo[KHOP * FF * GN];

__device__ __forceinline__ float elu1(float x) { return x > 0.f ? x : expm1f(x); }

// ---------------- small kernels (pipeline front) ----------------

__global__ void zero_kernel() {
    int i = blockIdx.x * blockDim.x + threadIdx.x;
    if (i < KHOP * NN) { g_deg[i] = 0; g_rowsum[i] = 0.f; }
}

__global__ void uv_kernel(const float* __restrict__ W, const float* __restrict__ a) {
    int z = blockIdx.x;
    int k = threadIdx.x;
    const float* wrow = W + (size_t)(z * FF + k) * GN;
    const float* au = a + z * 2 * FF;
    const float* av = au + FF;
    float u = 0.f, v = 0.f;
    #pragma unroll 8
    for (int j = 0; j < FF; j++) {
        float w = wrow[j];
        u = fmaf(w, au[j], u);
        v = fmaf(w, av[j], v);
    }
    g_u[z * FF + k] = u;
    g_v[z * FF + k] = v;
}

__global__ void __launch_bounds__(256) scores_kernel(const float* __restrict__ X) {
    __shared__ float su[KHOP][FF];
    __shared__ float sv[KHOP][FF];
    int tid = threadIdx.x;
    for (int i = tid; i < KHOP * FF; i += 256) {
        su[i / FF][i % FF] = g_u[i];
        sv[i / FF][i % FF] = g_v[i];
    }
    __syncthreads();
    int warp = tid >> 5, lane = tid & 31;
    int n = blockIdx.x * 8 + warp;
    if (n >= NN) return;
    float xr[8];
    #pragma unroll
    for (int j = 0; j < 8; j++) xr[j] = X[(size_t)n * FF + j * 32 + lane];
    #pragma unroll
    for (int z = 0; z < KHOP; z++) {
        float du = 0.f, dv = 0.f;
        #pragma unroll
        for (int j = 0; j < 8; j++) {
            du = fmaf(xr[j], su[z][j * 32 + lane], du);
            dv = fmaf(xr[j], sv[z][j * 32 + lane], dv);
        }
        #pragma unroll
        for (int off = 16; off > 0; off >>= 1) {
            du += __shfl_xor_sync(0xFFFFFFFFu, du, off);
            dv += __shfl_xor_sync(0xFFFFFFFFu, dv, off);
        }
        if (lane == 0) {
            g_s_src[z * NN + n] = du;
            g_s_dst[z * NN + n] = dv;
        }
    }
}

__global__ void hist_kernel(const int* __restrict__ kel) {
    int z = blockIdx.y;
    int e = blockIdx.x * 256 + threadIdx.x;
    if (e >= EE) return;
    int src = kel[(size_t)z * 2 * EE + e];
    atomicAdd(&g_deg[z * NN + src], 1);
}

__global__ void __launch_bounds__(1024) scan_kernel() {
    int z = blockIdx.x;
    __shared__ int wsum[32];
    int tid = threadIdx.x, lane = tid & 31, wid = tid >> 5;
    int carry = 0;
    for (int base = 0; base < NN; base += 1024) {
        int i = base + tid;
        int v = (i < NN) ? g_deg[z * NN + i] : 0;
        int x = v;
        #pragma unroll
        for (int off = 1; off < 32; off <<= 1) {
            int t = __shfl_up_sync(0xFFFFFFFFu, x, off);
            if (lane >= off) x += t;
        }
        if (lane == 31) wsum[wid] = x;
        __syncthreads();
        if (wid == 0) {
            int s = wsum[lane];
            #pragma unroll
            for (int off = 1; off < 32; off <<= 1) {
                int t = __shfl_up_sync(0xFFFFFFFFu, s, off);
                if (lane >= off) s += t;
            }
            wsum[lane] = s;
        }
        __syncthreads();
        int woff = wid ? wsum[wid - 1] : 0;
        int excl = carry + woff + x - v;
        if (i < NN) { g_ptr[z * NN + i] = excl; g_fill[z * NN + i] = excl; }
        int tot = wsum[31];
        __syncthreads();
        carry += tot;
    }
}

__global__ void build_kernel(const int* __restrict__ kel) {
    int z = blockIdx.y;
    int e = blockIdx.x * 256 + threadIdx.x;
    if (e >= EE) return;
    int src = kel[(size_t)z * 2 * EE + e];
    int dst = kel[(size_t)z * 2 * EE + EE + e];
    float sc = g_s_src[z * NN + src] + g_s_dst[z * NN + dst];
    float l = sc > 0.f ? sc : 0.2f * sc;           // leaky_relu(alpha=0.2)
    float w = expf(-l);
    int idx = atomicAdd(&g_fill[z * NN + src], 1);
    g_csr[(size_t)z * EE + idx] = make_int2(dst, __float_as_int(w));
    atomicAdd(&g_rowsum[z * NN + src], w);
}

// ---------------- bf16 split conversion ----------------

__device__ __forceinline__ uint32_t pkbf2(float a, float b) {
    __nv_bfloat162 t = __floats2bfloat162_rn(a, b);
    return *(uint32_t*)&t;
}

__global__ void __launch_bounds__(256) convX_kernel(const float* __restrict__ X) {
    size_t i = ((size_t)blockIdx.x * 256 + threadIdx.x) * 4;
    if (i >= (size_t)NN * FF) return;
    float4 v = *(const float4*)(X + i);
    float hx = __bfloat162float(__float2bfloat16_rn(v.x));
    float hy = __bfloat162float(__float2bfloat16_rn(v.y));
    float hz = __bfloat162float(__float2bfloat16_rn(v.z));
    float hw = __bfloat162float(__float2bfloat16_rn(v.w));
    uint2 hi = make_uint2(pkbf2(v.x, v.y), pkbf2(v.z, v.w));
    uint2 lo = make_uint2(pkbf2(v.x - hx, v.y - hy), pkbf2(v.z - hz, v.w - hw));
    *(uint2*)(g_Xhi + i) = hi;
    *(uint2*)(g_Xlo + i) = lo;
}

__global__ void __launch_bounds__(256) convW_kernel(const float* __restrict__ W) {
    int idx = blockIdx.x * 256 + threadIdx.x;
    if (idx >= KHOP * FF * GN) return;
    int z = idx >> 16;
    int rem = idx & 65535;
    int k = rem >> 8;
    int n = rem & 255;
    float w = W[(size_t)(z * FF + k) * GN + n];
    float hf = __bfloat162float(__float2bfloat16_rn(w));
    g_Wthi[z * 65536 + n * 256 + k] = __float2bfloat16_rn(w);
    g_Wtlo[z * 65536 + n * 256 + k] = __float2bfloat16_rn(w - hf);
}

// ---------------- mma.sync bf16 GEMM (base-ISA HMMA; sm_103-safe) ----------------
// Y[128-tile, 128-tile] = X @ W_z via m16n8k16 row.col f32.bf16.bf16.f32
// hi/lo split: acc = Ahi*Bhi + Ahi*Blo + Alo*Bhi  (lo*lo dropped)

#define SAW 40   // smem row pitch in bf16 (80 B: 16B-aligned, conflict-free frag reads)

__device__ __forceinline__ void mma16816(float* c, const uint32_t* a, const uint32_t* b) {
    asm volatile(
        "mma.sync.aligned.m16n8k16.row.col.f32.bf16.bf16.f32 "
        "{%0,%1,%2,%3}, {%4,%5,%6,%7}, {%8,%9}, {%0,%1,%2,%3};"
        : "+f"(c[0]), "+f"(c[1]), "+f"(c[2]), "+f"(c[3])
        : "r"(a[0]), "r"(a[1]), "r"(a[2]), "r"(a[3]), "r"(b[0]), "r"(b[1]));
}

__global__ void __launch_bounds__(256) gemm_mma_kernel(int z, float* __restrict__ Y) {
    __shared__ __nv_bfloat16 sAhi[128 * SAW];
    __shared__ __nv_bfloat16 sAlo[128 * SAW];
    __shared__ __nv_bfloat16 sBhi[128 * SAW];
    __shared__ __nv_bfloat16 sBlo[128 * SAW];

    const int tid = threadIdx.x;
    const int wid = tid >> 5, lane = tid & 31;
    const int g = lane >> 2, tg = lane & 3;       // groupID, threadID-in-group
    const int warp_m = wid >> 2;                  // 0..1
    const int warp_n = wid & 3;                   // 0..3
    const int rowBase = blockIdx.x * 128;
    const int colBase = blockIdx.y * 128;

    const __nv_bfloat16* Wth = g_Wthi + (size_t)z * 65536;
    const __nv_bfloat16* Wtl = g_Wtlo + (size_t)z * 65536;

    float c[4][4][4];
    #pragma unroll
    for (int mt = 0; mt < 4; mt++)
        #pragma unroll
        for (int nt = 0; nt < 4; nt++)
            #pragma unroll
            for (int q = 0; q < 4; q++) c[mt][nt][q] = 0.f;

    for (int kc = 0; kc < 8; kc++) {
        const int k0g = kc * 32;
        // load A tile: 128 rows x 32 bf16 (hi+lo). 512 uint4 per tile, 2 per thread.
        #pragma unroll
        for (int it = 0; it < 2; it++) {
            int q = tid + it * 256;               // 0..511
            int r = q >> 2, s = q & 3;
            int row_g = rowBase + r;
            uint4 vh = make_uint4(0, 0, 0, 0), vl = make_uint4(0, 0, 0, 0);
            if (row_g < NN) {
                size_t go = (size_t)row_g * FF + k0g + s * 8;
                vh = *(const uint4*)(g_Xhi + go);
                vl = *(const uint4*)(g_Xlo + go);
            }
            *(uint4*)(sAhi + r * SAW + s * 8) = vh;
            *(uint4*)(sAlo + r * SAW + s * 8) = vl;
        }
        // load B tile: 128 n-rows x 32 k bf16 (hi+lo)
        #pragma unroll
        for (int it = 0; it < 2; it++) {
            int q = tid + it * 256;
            int r = q >> 2, s = q & 3;            // n-row, k-seg
            size_t go = (size_t)(colBase + r) * 256 + k0g + s * 8;
            *(uint4*)(sBhi + r * SAW + s * 8) = *(const uint4*)(Wth + go);
            *(uint4*)(sBlo + r * SAW + s * 8) = *(const uint4*)(Wtl + go);
        }
        __syncthreads();

        #pragma unroll
        for (int ks = 0; ks < 2; ks++) {
            const int k0 = ks * 16;
            uint32_t ah[4][4], al[4][4];
            #pragma unroll
            for (int mt = 0; mt < 4; mt++) {
                int r0 = warp_m * 64 + mt * 16 + g;
                int kk = k0 + tg * 2;
                ah[mt][0] = *(const uint32_t*)(sAhi + r0 * SAW + kk);
                ah[mt][1] = *(const uint32_t*)(sAhi + (r0 + 8) * SAW + kk);
                ah[mt][2] = *(const uint32_t*)(sAhi + r0 * SAW + kk + 8);
                ah[mt][3] = *(const uint32_t*)(sAhi + (r0 + 8) * SAW + kk + 8);
                al[mt][0] = *(const uint32_t*)(sAlo + r0 * SAW + kk);
                al[mt][1] = *(const uint32_t*)(sAlo + (r0 + 8) * SAW + kk);
                al[mt][2] = *(const uint32_t*)(sAlo + r0 * SAW + kk + 8);
                al[mt][3] = *(const uint32_t*)(sAlo + (r0 + 8) * SAW + kk + 8);
            }
            uint32_t bh[4][2], bl[4][2];
            #pragma unroll
            for (int nt = 0; nt < 4; nt++) {
                int n0 = warp_n * 32 + nt * 8 + g;
                int kk = k0 + tg * 2;
                bh[nt][0] = *(const uint32_t*)(sBhi + n0 * SAW + kk);
                bh[nt][1] = *(const uint32_t*)(sBhi + n0 * SAW + kk + 8);
                bl[nt][0] = *(const uint32_t*)(sBlo + n0 * SAW + kk);
                bl[nt][1] = *(const uint32_t*)(sBlo + n0 * SAW + kk + 8);
            }
            #pragma unroll
            for (int mt = 0; mt < 4; mt++)
                #pragma unroll
                for (int nt = 0; nt < 4; nt++) {
                    mma16816(c[mt][nt], ah[mt], bh[nt]);
                    mma16816(c[mt][nt], ah[mt], bl[nt]);
                    mma16816(c[mt][nt], al[mt], bh[nt]);
                }
        }
        __syncthreads();
    }

    // epilogue: direct float2 stores
    #pragma unroll
    for (int mt = 0; mt < 4; mt++) {
        int r0 = rowBase + warp_m * 64 + mt * 16 + g;
        #pragma unroll
        for (int nt = 0; nt < 4; nt++) {
            int col = colBase + warp_n * 32 + nt * 8 + tg * 2;
            if (r0 < NN)
                *(float2*)(Y + (size_t)r0 * GN + col) = make_float2(c[mt][nt][0], c[mt][nt][1]);
            if (r0 + 8 < NN)
                *(float2*)(Y + (size_t)(r0 + 8) * GN + col) = make_float2(c[mt][nt][2], c[mt][nt][3]);
        }
    }
}

// ---------------- aggregation (out space) ----------------
__global__ void __launch_bounds__(256) aggregate_kernel(const float* __restrict__ Y,
                                                        int z, float coef, int mode,
                                                        float* __restrict__ dst_buf) {
    const int n = blockIdx.x;
    const int tid = threadIdx.x;
    __shared__ int2 se[128];
    const int start = g_ptr[z * NN + n];
    const int d     = g_deg[z * NN + n];
    const int2* __restrict__ ce = g_csr + (size_t)z * EE + start;
    float acc = 0.f;
    for (int base = 0; base < d; base += 128) {
        int cnt = min(128, d - base);
        __syncthreads();
        if (tid < cnt) se[tid] = ce[base + tid];
        __syncthreads();
        int j = 0;
        for (; j + 4 <= cnt; j += 4) {
            int2 e0 = se[j + 0], e1 = se[j + 1], e2 = se[j + 2], e3 = se[j + 3];
            float x0 = Y[(size_t)e0.x * FF + tid];
            float x1 = Y[(size_t)e1.x * FF + tid];
            float x2 = Y[(size_t)e2.x * FF + tid];
            float x3 = Y[(size_t)e3.x * FF + tid];
            acc = fmaf(__int_as_float(e0.y), x0, acc);
            acc = fmaf(__int_as_float(e1.y), x1, acc);
            acc = fmaf(__int_as_float(e2.y), x2, acc);
            acc = fmaf(__int_as_float(e3.y), x3, acc);
        }
        for (; j < cnt; j++)
            acc = fmaf(__int_as_float(se[j].y), Y[(size_t)se[j].x * FF + tid], acc);
    }
    float val = coef * acc / g_rowsum[z * NN + n];
    size_t o = (size_t)n * FF + tid;
    if (mode == 0)      g_hacc[o] = val;
    else if (mode == 1) g_hacc[o] += val;
    else                dst_buf[o] = elu1(g_hacc[o] + val);
}

// ---------------- launch ----------------
extern "C" void kernel_launch(void* const* d_in, const int* in_sizes, int n_in,
                              void* d_out, int out_size) {
    const float* X   = (const float*)d_in[0];
    const int*   kel = (const int*)d_in[1];
    const float* W   = (const float*)d_in[2];
    const float* a   = (const float*)d_in[3];
    float* out = (float*)d_out;

    zero_kernel<<<(KHOP * NN + 255) / 256, 256>>>();
    uv_kernel<<<KHOP, 256>>>(W, a);
    scores_kernel<<<NN / 8, 256>>>(X);
    convX_kernel<<<(NN * FF / 4 + 255) / 256, 256>>>(X);
    convW_kernel<<<(KHOP * FF * GN + 255) / 256, 256>>>(W);
    hist_kernel<<<dim3(EE / 256, KHOP), 256>>>(kel);
    scan_kernel<<<KHOP, 1024>>>();
    build_kernel<<<dim3(EE / 256, KHOP), 256>>>(kel);

    float* Y;
    cudaGetSymbolAddress((void**)&Y, g_Y);
    const float coef[KHOP] = {0.5f, 0.25f, 0.125f};
    for (int z = 0; z < KHOP; z++) {
        gemm_mma_kernel<<<dim3((NN + 127) / 128, GN / 128), 256>>>(z, Y);
        aggregate_kernel<<<NN, 256>>>(Y, z, coef[z], (z == KHOP - 1) ? 2 : (z == 0 ? 0 : 1), out);
    }
}

// round 7
// speedup vs baseline: 1.4714x; 1.0677x over previous
#include <cuda_runtime.h>
#include <cuda_bf16.h>
#include <cuda_fp16.h>
#include <math.h>
#include <stdint.h>

#define NN 50000
#define EE 1600000
#define FF 256
#define KHOP 3
#define GN 256

// ---------------- scratch (device globals; no allocations allowed) ----------------
__device__ float g_u[KHOP * FF];
__device__ float g_v[KHOP * FF];
__device__ float g_s_src[KHOP * NN];
__device__ float g_s_dst[KHOP * NN];
__device__ float g_rowsum[KHOP * NN];
__device__ int   g_deg[KHOP * NN];
__device__ int   g_ptr[KHOP * NN];
__device__ int   g_fill[KHOP * NN];
__device__ int2  g_csr[(size_t)KHOP * EE + 32];      // (dst, w-as-int); +32 pad for warp over-read
__device__ __half g_Yh[(size_t)KHOP * NN * FF];      // per-hop Y = X @ W_z, fp16
__device__ __nv_bfloat16 g_Xhi[(size_t)NN * FF];
__device__ __nv_bfloat16 g_Xlo[(size_t)NN * FF];
__device__ __nv_bfloat16 g_Wthi[KHOP * FF * GN];     // transposed: [z][n][k]
__device__ __nv_bfloat16 g_Wtlo[KHOP * FF * GN];

__device__ __forceinline__ float elu1(float x) { return x > 0.f ? x : expm1f(x); }

// ---------------- small kernels (pipeline front) ----------------

__global__ void zero_kernel() {
    int i = blockIdx.x * blockDim.x + threadIdx.x;
    if (i < KHOP * NN) { g_deg[i] = 0; g_rowsum[i] = 0.f; }
}

__global__ void uv_kernel(const float* __restrict__ W, const float* __restrict__ a) {
    int z = blockIdx.x;
    int k = threadIdx.x;
    const float* wrow = W + (size_t)(z * FF + k) * GN;
    const float* au = a + z * 2 * FF;
    const float* av = au + FF;
    float u = 0.f, v = 0.f;
    #pragma unroll 8
    for (int j = 0; j < FF; j++) {
        float w = wrow[j];
        u = fmaf(w, au[j], u);
        v = fmaf(w, av[j], v);
    }
    g_u[z * FF + k] = u;
    g_v[z * FF + k] = v;
}

__global__ void __launch_bounds__(256) scores_kernel(const float* __restrict__ X) {
    __shared__ float su[KHOP][FF];
    __shared__ float sv[KHOP][FF];
    int tid = threadIdx.x;
    for (int i = tid; i < KHOP * FF; i += 256) {
        su[i / FF][i % FF] = g_u[i];
        sv[i / FF][i % FF] = g_v[i];
    }
    __syncthreads();
    int warp = tid >> 5, lane = tid & 31;
    int n = blockIdx.x * 8 + warp;
    if (n >= NN) return;
    float xr[8];
    #pragma unroll
    for (int j = 0; j < 8; j++) xr[j] = X[(size_t)n * FF + j * 32 + lane];
    #pragma unroll
    for (int z = 0; z < KHOP; z++) {
        float du = 0.f, dv = 0.f;
        #pragma unroll
        for (int j = 0; j < 8; j++) {
            du = fmaf(xr[j], su[z][j * 32 + lane], du);
            dv = fmaf(xr[j], sv[z][j * 32 + lane], dv);
        }
        #pragma unroll
        for (int off = 16; off > 0; off >>= 1) {
            du += __shfl_xor_sync(0xFFFFFFFFu, du, off);
            dv += __shfl_xor_sync(0xFFFFFFFFu, dv, off);
        }
        if (lane == 0) {
            g_s_src[z * NN + n] = du;
            g_s_dst[z * NN + n] = dv;
        }
    }
}

__global__ void hist_kernel(const int* __restrict__ kel) {
    int z = blockIdx.y;
    int e = blockIdx.x * 256 + threadIdx.x;
    if (e >= EE) return;
    int src = kel[(size_t)z * 2 * EE + e];
    atomicAdd(&g_deg[z * NN + src], 1);
}

__global__ void __launch_bounds__(1024) scan_kernel() {
    int z = blockIdx.x;
    __shared__ int wsum[32];
    int tid = threadIdx.x, lane = tid & 31, wid = tid >> 5;
    int carry = 0;
    for (int base = 0; base < NN; base += 1024) {
        int i = base + tid;
        int v = (i < NN) ? g_deg[z * NN + i] : 0;
        int x = v;
        #pragma unroll
        for (int off = 1; off < 32; off <<= 1) {
            int t = __shfl_up_sync(0xFFFFFFFFu, x, off);
            if (lane >= off) x += t;
        }
        if (lane == 31) wsum[wid] = x;
        __syncthreads();
        if (wid == 0) {
            int s = wsum[lane];
            #pragma unroll
            for (int off = 1; off < 32; off <<= 1) {
                int t = __shfl_up_sync(0xFFFFFFFFu, s, off);
                if (lane >= off) s += t;
            }
            wsum[lane] = s;
        }
        __syncthreads();
        int woff = wid ? wsum[wid - 1] : 0;
        int excl = carry + woff + x - v;
        if (i < NN) { g_ptr[z * NN + i] = excl; g_fill[z * NN + i] = excl; }
        int tot = wsum[31];
        __syncthreads();
        carry += tot;
    }
}

__global__ void build_kernel(const int* __restrict__ kel) {
    int z = blockIdx.y;
    int e = blockIdx.x * 256 + threadIdx.x;
    if (e >= EE) return;
    int src = kel[(size_t)z * 2 * EE + e];
    int dst = kel[(size_t)z * 2 * EE + EE + e];
    float sc = g_s_src[z * NN + src] + g_s_dst[z * NN + dst];
    float l = sc > 0.f ? sc : 0.2f * sc;           // leaky_relu(alpha=0.2)
    float w = expf(-l);
    int idx = atomicAdd(&g_fill[z * NN + src], 1);
    g_csr[(size_t)z * EE + idx] = make_int2(dst, __float_as_int(w));
    atomicAdd(&g_rowsum[z * NN + src], w);
}

// ---------------- bf16 split conversion ----------------

__device__ __forceinline__ uint32_t pkbf2(float a, float b) {
    __nv_bfloat162 t = __floats2bfloat162_rn(a, b);
    return *(uint32_t*)&t;
}
__device__ __forceinline__ uint32_t pkh2(float a, float b) {
    __half2 t = __floats2half2_rn(a, b);
    return *(uint32_t*)&t;
}

__global__ void __launch_bounds__(256) convX_kernel(const float* __restrict__ X) {
    size_t i = ((size_t)blockIdx.x * 256 + threadIdx.x) * 4;
    if (i >= (size_t)NN * FF) return;
    float4 v = *(const float4*)(X + i);
    float hx = __bfloat162float(__float2bfloat16_rn(v.x));
    float hy = __bfloat162float(__float2bfloat16_rn(v.y));
    float hz = __bfloat162float(__float2bfloat16_rn(v.z));
    float hw = __bfloat162float(__float2bfloat16_rn(v.w));
    uint2 hi = make_uint2(pkbf2(v.x, v.y), pkbf2(v.z, v.w));
    uint2 lo = make_uint2(pkbf2(v.x - hx, v.y - hy), pkbf2(v.z - hz, v.w - hw));
    *(uint2*)(g_Xhi + i) = hi;
    *(uint2*)(g_Xlo + i) = lo;
}

__global__ void __launch_bounds__(256) convW_kernel(const float* __restrict__ W) {
    int idx = blockIdx.x * 256 + threadIdx.x;
    if (idx >= KHOP * FF * GN) return;
    int z = idx >> 16;
    int rem = idx & 65535;
    int k = rem >> 8;
    int n = rem & 255;
    float w = W[(size_t)(z * FF + k) * GN + n];
    float hf = __bfloat162float(__float2bfloat16_rn(w));
    g_Wthi[z * 65536 + n * 256 + k] = __float2bfloat16_rn(w);
    g_Wtlo[z * 65536 + n * 256 + k] = __float2bfloat16_rn(w - hf);
}

// ---------------- mma.sync bf16 GEMM (base-ISA HMMA; sm_103-safe) ----------------
// Yh_z[128-tile, 128-tile] = X @ W_z via m16n8k16 row.col f32.bf16.bf16.f32
// hi/lo split: acc = Ahi*Bhi + Ahi*Blo + Alo*Bhi  (lo*lo dropped); fp16 output

#define SAW 40   // smem row pitch in bf16 (80 B: 16B-aligned, conflict-free frag reads)

__device__ __forceinline__ void mma16816(float* c, const uint32_t* a, const uint32_t* b) {
    asm volatile(
        "mma.sync.aligned.m16n8k16.row.col.f32.bf16.bf16.f32 "
        "{%0,%1,%2,%3}, {%4,%5,%6,%7}, {%8,%9}, {%0,%1,%2,%3};"
        : "+f"(c[0]), "+f"(c[1]), "+f"(c[2]), "+f"(c[3])
        : "r"(a[0]), "r"(a[1]), "r"(a[2]), "r"(a[3]), "r"(b[0]), "r"(b[1]));
}

__global__ void __launch_bounds__(256) gemm_mma_kernel() {
    __shared__ __nv_bfloat16 sAhi[128 * SAW];
    __shared__ __nv_bfloat16 sAlo[128 * SAW];
    __shared__ __nv_bfloat16 sBhi[128 * SAW];
    __shared__ __nv_bfloat16 sBlo[128 * SAW];

    const int tid = threadIdx.x;
    const int wid = tid >> 5, lane = tid & 31;
    const int g = lane >> 2, tg = lane & 3;       // groupID, threadID-in-group
    const int warp_m = wid >> 2;                  // 0..1
    const int warp_n = wid & 3;                   // 0..3
    const int rowBase = blockIdx.x * 128;
    const int colBase = blockIdx.y * 128;
    const int z = blockIdx.z;

    const __nv_bfloat16* Wth = g_Wthi + (size_t)z * 65536;
    const __nv_bfloat16* Wtl = g_Wtlo + (size_t)z * 65536;
    __half* Yh = g_Yh + (size_t)z * NN * FF;

    float c[4][4][4];
    #pragma unroll
    for (int mt = 0; mt < 4; mt++)
        #pragma unroll
        for (int nt = 0; nt < 4; nt++)
            #pragma unroll
            for (int q = 0; q < 4; q++) c[mt][nt][q] = 0.f;

    for (int kc = 0; kc < 8; kc++) {
        const int k0g = kc * 32;
        #pragma unroll
        for (int it = 0; it < 2; it++) {
            int q = tid + it * 256;               // 0..511
            int r = q >> 2, s = q & 3;
            int row_g = rowBase + r;
            uint4 vh = make_uint4(0, 0, 0, 0), vl = make_uint4(0, 0, 0, 0);
            if (row_g < NN) {
                size_t go = (size_t)row_g * FF + k0g + s * 8;
                vh = *(const uint4*)(g_Xhi + go);
                vl = *(const uint4*)(g_Xlo + go);
            }
            *(uint4*)(sAhi + r * SAW + s * 8) = vh;
            *(uint4*)(sAlo + r * SAW + s * 8) = vl;
        }
        #pragma unroll
        for (int it = 0; it < 2; it++) {
            int q = tid + it * 256;
            int r = q >> 2, s = q & 3;            // n-row, k-seg
            size_t go = (size_t)(colBase + r) * 256 + k0g + s * 8;
            *(uint4*)(sBhi + r * SAW + s * 8) = *(const uint4*)(Wth + go);
            *(uint4*)(sBlo + r * SAW + s * 8) = *(const uint4*)(Wtl + go);
        }
        __syncthreads();

        #pragma unroll
        for (int ks = 0; ks < 2; ks++) {
            const int k0 = ks * 16;
            uint32_t ah[4][4], al[4][4];
            #pragma unroll
            for (int mt = 0; mt < 4; mt++) {
                int r0 = warp_m * 64 + mt * 16 + g;
                int kk = k0 + tg * 2;
                ah[mt][0] = *(const uint32_t*)(sAhi + r0 * SAW + kk);
                ah[mt][1] = *(const uint32_t*)(sAhi + (r0 + 8) * SAW + kk);
                ah[mt][2] = *(const uint32_t*)(sAhi + r0 * SAW + kk + 8);
                ah[mt][3] = *(const uint32_t*)(sAhi + (r0 + 8) * SAW + kk + 8);
                al[mt][0] = *(const uint32_t*)(sAlo + r0 * SAW + kk);
                al[mt][1] = *(const uint32_t*)(sAlo + (r0 + 8) * SAW + kk);
                al[mt][2] = *(const uint32_t*)(sAlo + r0 * SAW + kk + 8);
                al[mt][3] = *(const uint32_t*)(sAlo + (r0 + 8) * SAW + kk + 8);
            }
            uint32_t bh[4][2], bl[4][2];
            #pragma unroll
            for (int nt = 0; nt < 4; nt++) {
                int n0 = warp_n * 32 + nt * 8 + g;
                int kk = k0 + tg * 2;
                bh[nt][0] = *(const uint32_t*)(sBhi + n0 * SAW + kk);
                bh[nt][1] = *(const uint32_t*)(sBhi + n0 * SAW + kk + 8);
                bl[nt][0] = *(const uint32_t*)(sBlo + n0 * SAW + kk);
                bl[nt][1] = *(const uint32_t*)(sBlo + n0 * SAW + kk + 8);
            }
            #pragma unroll
            for (int mt = 0; mt < 4; mt++)
                #pragma unroll
                for (int nt = 0; nt < 4; nt++) {
                    mma16816(c[mt][nt], ah[mt], bh[nt]);
                    mma16816(c[mt][nt], ah[mt], bl[nt]);
                    mma16816(c[mt][nt], al[mt], bh[nt]);
                }
        }
        __syncthreads();
    }

    // epilogue: pack to fp16, 4-byte stores
    #pragma unroll
    for (int mt = 0; mt < 4; mt++) {
        int r0 = rowBase + warp_m * 64 + mt * 16 + g;
        #pragma unroll
        for (int nt = 0; nt < 4; nt++) {
            int col = colBase + warp_n * 32 + nt * 8 + tg * 2;
            if (r0 < NN)
                *(uint32_t*)(Yh + (size_t)r0 * GN + col) = pkh2(c[mt][nt][0], c[mt][nt][1]);
            if (r0 + 8 < NN)
                *(uint32_t*)(Yh + (size_t)(r0 + 8) * GN + col) = pkh2(c[mt][nt][2], c[mt][nt][3]);
        }
    }
}

// ---------------- fused 3-hop aggregation: warp per node ----------------
// out[n] = elu( sum_z coef_z/rowsum_z(n) * sum_e w_e Yh_z[dst_e] )
__global__ void __launch_bounds__(256) aggregate_fused_kernel(float* __restrict__ out) {
    const int wid = threadIdx.x >> 5, lane = threadIdx.x & 31;
    const int n = blockIdx.x * 8 + wid;
    if (n >= NN) return;

    float tot[8];
    #pragma unroll
    for (int t = 0; t < 8; t++) tot[t] = 0.f;

    #pragma unroll
    for (int z = 0; z < KHOP; z++) {
        const int start = g_ptr[z * NN + n];
        const int d     = g_deg[z * NN + n];
        const int2* __restrict__ ce = g_csr + (size_t)z * EE + start;
        const __half* __restrict__ Yz = g_Yh + (size_t)z * NN * FF;

        float acc[8];
        #pragma unroll
        for (int t = 0; t < 8; t++) acc[t] = 0.f;

        for (int base = 0; base < d; base += 32) {
            int cnt = min(32, d - base);
            int2 e = ce[base + lane];            // pad at array end makes this safe
            #pragma unroll 4
            for (int k = 0; k < cnt; k++) {
                int   dst = __shfl_sync(0xFFFFFFFFu, e.x, k);
                float w   = __int_as_float(__shfl_sync(0xFFFFFFFFu, e.y, k));
                uint4 v = *(const uint4*)(Yz + (size_t)dst * FF + lane * 8);
                float2 f0 = __half22float2(*(__half2*)&v.x);
                float2 f1 = __half22float2(*(__half2*)&v.y);
                float2 f2 = __half22float2(*(__half2*)&v.z);
                float2 f3 = __half22float2(*(__half2*)&v.w);
                acc[0] = fmaf(w, f0.x, acc[0]);
                acc[1] = fmaf(w, f0.y, acc[1]);
                acc[2] = fmaf(w, f1.x, acc[2]);
                acc[3] = fmaf(w, f1.y, acc[3]);
                acc[4] = fmaf(w, f2.x, acc[4]);
                acc[5] = fmaf(w, f2.y, acc[5]);
                acc[6] = fmaf(w, f3.x, acc[6]);
                acc[7] = fmaf(w, f3.y, acc[7]);
            }
        }
        const float coef = (z == 0) ? 0.5f : (z == 1) ? 0.25f : 0.125f;
        float s = coef / g_rowsum[z * NN + n];
        #pragma unroll
        for (int t = 0; t < 8; t++) tot[t] = fmaf(acc[t], s, tot[t]);
    }

    float4 o0 = make_float4(elu1(tot[0]), elu1(tot[1]), elu1(tot[2]), elu1(tot[3]));
    float4 o1 = make_float4(elu1(tot[4]), elu1(tot[5]), elu1(tot[6]), elu1(tot[7]));
    float* dst = out + (size_t)n * FF + lane * 8;
    *(float4*)dst = o0;
    *(float4*)(dst + 4) = o1;
}

// ---------------- launch ----------------
extern "C" void kernel_launch(void* const* d_in, const int* in_sizes, int n_in,
                              void* d_out, int out_size) {
    const float* X   = (const float*)d_in[0];
    const int*   kel = (const int*)d_in[1];
    const float* W   = (const float*)d_in[2];
    const float* a   = (const float*)d_in[3];
    float* out = (float*)d_out;

    zero_kernel<<<(KHOP * NN + 255) / 256, 256>>>();
    uv_kernel<<<KHOP, 256>>>(W, a);
    scores_kernel<<<NN / 8, 256>>>(X);
    convX_kernel<<<(NN * FF / 4 + 255) / 256, 256>>>(X);
    convW_kernel<<<(KHOP * FF * GN + 255) / 256, 256>>>(W);
    hist_kernel<<<dim3(EE / 256, KHOP), 256>>>(kel);
    scan_kernel<<<KHOP, 1024>>>();
    build_kernel<<<dim3(EE / 256, KHOP), 256>>>(kel);

    gemm_mma_kernel<<<dim3((NN + 127) / 128, GN / 128, KHOP), 256>>>();
    aggregate_fused_kernel<<<(NN + 7) / 8, 256>>>(out);
}